// round 15
// baseline (speedup 1.0000x reference)
#include <cuda_runtime.h>
#include <cuda_fp16.h>
#include <cstdint>

// LSTMPredictor R14: WARP-LOCAL recurrence — zero CTA barriers in the time loop.
// Each warp owns 16 batch rows and computes the FULL gate GEMV (all 26 n-tiles,
// both layers) for them; h round-trips through the warp's private SMEM A-tile
// (ldmatrix transpose), c-state + output weights in registers, weights re-read
// from SMEM each step as 2x LDS.128 per (tile,layer) (kt-contiguous layout).
// Gate-pair permutation (R13): activation needs no shuffles.
//
// Grid 128 CTAs x 128 thr (4 warps), 16 rows/warp -> 512 warps = 8192 rows.
// fp16 mma.m16n8k16: G[16 x 208] = A[16 x 64] @ W.
//   K: 0..50 h, 51 x/out, 52 bias(1.0), 53..63 zero
//   N tiles: pair p = nt>>1, half hh = nt&1; col cl: jl=cl>>1, gpar=cl&1;
//   j = 4p+jl, gate q' = hh*2+gpar (i,f,g,o); sigmoid rows pre-scaled 0.5.

#define TSEQ 2048
#define TTOT 2112
#define TPB  128
#define NCTA 128
#define ASTR 72
#define AHALF 1152            // halves per A buffer (16*72)

__device__ __align__(16) uint32_t d_Wf[16384];

__device__ __forceinline__ float tanh_ap(float x) {
    float y; asm("tanh.approx.f32 %0, %1;" : "=f"(y) : "f"(x)); return y;
}
__device__ __forceinline__ __half2 tanh2_ap(__half2 a) {
    uint32_t r, u = *(uint32_t*)&a;
    asm("tanh.approx.f16x2 %0, %1;" : "=r"(r) : "r"(u));
    return *(__half2*)&r;
}

#define LDSM4(d, addr)                                                        \
    asm volatile("ldmatrix.sync.aligned.m8n8.x4.shared.b16 {%0,%1,%2,%3}, [%4];" \
                 : "=r"(d[0]), "=r"(d[1]), "=r"(d[2]), "=r"(d[3]) : "r"(addr))

#define LDSM1(d, addr)                                                        \
    asm volatile("ldmatrix.sync.aligned.m8n8.x4.shared.b16 {%0,%1,%2,%3}, [%4];" \
                 : "=r"(d[0]), "=r"(d[1]), "=r"(d[2]), "=r"(d[3]) : "r"(addr))

#define MMA1(d0, d1, d2, d3, a0, a1, a2, a3, b0, b1)                          \
    asm volatile(                                                             \
        "mma.sync.aligned.m16n8k16.row.col.f32.f16.f16.f32 "                  \
        "{%0,%1,%2,%3},{%4,%5,%6,%7},{%8,%9},{%0,%1,%2,%3};\n"                \
        : "+f"(d0), "+f"(d1), "+f"(d2), "+f"(d3)                              \
        : "r"(a0), "r"(a1), "r"(a2), "r"(a3), "r"(b0), "r"(b1))

// Load both tiles of pair p (layer base Wp) and run the two 4-deep mma chains.
#define MMA_PAIR(Wp, A0, A1, A2, A3, B0, B1, B2, B3)                          \
    do {                                                                      \
        uint4 _e0 = (Wp)[lane];                                               \
        uint4 _e1 = (Wp)[32 + lane];                                          \
        uint4 _o0 = (Wp)[64 + lane];                                          \
        uint4 _o1 = (Wp)[96 + lane];                                          \
        MMA1(A0, A1, A2, A3, a[0][0], a[0][1], a[0][2], a[0][3], _e0.x, _e1.x); \
        MMA1(A0, A1, A2, A3, a[1][0], a[1][1], a[1][2], a[1][3], _e0.y, _e1.y); \
        MMA1(A0, A1, A2, A3, a[2][0], a[2][1], a[2][2], a[2][3], _e0.z, _e1.z); \
        MMA1(A0, A1, A2, A3, a[3][0], a[3][1], a[3][2], a[3][3], _e0.w, _e1.w); \
        MMA1(B0, B1, B2, B3, a[0][0], a[0][1], a[0][2], a[0][3], _o0.x, _o1.x); \
        MMA1(B0, B1, B2, B3, a[1][0], a[1][1], a[1][2], a[1][3], _o0.y, _o1.y); \
        MMA1(B0, B1, B2, B3, a[2][0], a[2][1], a[2][2], a[2][3], _o0.z, _o1.z); \
        MMA1(B0, B1, B2, B3, a[3][0], a[3][1], a[3][2], a[3][3], _o0.w, _o1.w); \
    } while (0)

// ---------------------------------------------------------------------------
// Weight prep, kt-contiguous uint4 layout:
// uint32 index u: kt = u&3, lane = (u>>2)&31, r = (u>>7)&1, nt = (u>>8)&31,
// L = (u>>13)&1. Gate-pair value mapping identical to R13 (verified):
// cl = lane>>2; p = nt>>1; hh = nt&1; jl = cl>>1; gpar = cl&1;
// j = 4p+jl; q' = hh*2+gpar; row = q'*51+j (j<51); k0 = kt*16+r*8+2*(lane&3);
// value pair (k0, k0+1); k<51 h-wt, k==51 x-wt (L1), k==52 bias; sigmoid
// gates (q' != 2) pre-scaled 0.5.
__global__ void prep_weights(const float* __restrict__ Wih1, const float* __restrict__ Whh1,
                             const float* __restrict__ bih1, const float* __restrict__ bhh1,
                             const float* __restrict__ Wih2, const float* __restrict__ Whh2,
                             const float* __restrict__ bih2, const float* __restrict__ bhh2) {
    int u = blockIdx.x * blockDim.x + threadIdx.x;
    if (u >= 16384) return;
    int kt   = u & 3;
    int lane = (u >> 2) & 31;
    int r    = (u >> 7) & 1;
    int nt   = (u >> 8) & 31;
    int L    = (u >> 13) & 1;
    int cl   = lane >> 2;
    int p    = nt >> 1, hh = nt & 1;
    int jl   = cl >> 1, gpar = cl & 1;
    int j    = p * 4 + jl;
    int qp   = hh * 2 + gpar;
    int k0   = kt * 16 + r * 8 + 2 * (lane & 3);
    float v[2];
#pragma unroll
    for (int i = 0; i < 2; i++) {
        int k = k0 + i;
        float val = 0.0f;
        if (j < 51) {
            int row = qp * 51 + j;
            if (k < 51)
                val = (L == 0) ? Whh1[row * 51 + k]
                               : (Wih2[row * 51 + k] + Whh2[row * 51 + k]);
            else if (k == 51)
                val = (L == 0) ? Wih1[row] : 0.0f;
            else if (k == 52)
                val = (L == 0) ? (bih1[row] + bhh1[row]) : (bih2[row] + bhh2[row]);
            if (qp != 2) val *= 0.5f;
        }
        v[i] = val;
    }
    __half2 h = __floats2half2_rn(v[0], v[1]);
    d_Wf[u] = *(uint32_t*)&h;
}

// ---------------------------------------------------------------------------
__device__ __forceinline__ void site_act(float gA0, float gA1, float gB0, float gB1,
                                         float& i_, float& f_, float& z_, float& o_) {
    const __half2 H05 = __float2half2_rn(0.5f);
    __half2 t1  = tanh2_ap(__floats2half2_rn(gA0, gA1));
    __half2 sif = __hfma2(t1, H05, H05);
    __half2 t2  = tanh2_ap(__floats2half2_rn(gB0, gB1));
    i_ = __low2float(sif);
    f_ = __high2float(sif);
    z_ = __low2float(t2);
    o_ = fmaf(__high2float(t2), 0.5f, 0.5f);
}

// ---------------------------------------------------------------------------
__global__ void __launch_bounds__(TPB, 1)
lstm_main(const float* __restrict__ x,
          const float* __restrict__ Wout, const float* __restrict__ bout,
          float* __restrict__ out) {
    extern __shared__ char sm[];
    uint4*  Wsm = (uint4*)sm;                       // 4096 uint4 = 64 KB
    __half* Aw  = (__half*)(sm + 65536);            // [4 warps][2][1152]

    const int tid  = threadIdx.x;
    const int lane = tid & 31;
    const int wrp  = tid >> 5;
    const int g    = lane >> 2, tig = lane & 3;
    const int rowbase = blockIdx.x * 64 + wrp * 16;

    // ---- weights GMEM -> SMEM (once) ----
    for (int i = tid; i < 4096; i += TPB) Wsm[i] = ((const uint4*)d_Wf)[i];

    // ---- this warp's A double buffer ----
    __half* myA = Aw + wrp * (2 * AHALF);
    const __half h1v = __float2half_rn(1.0f);
    const __half h0v = __float2half_rn(0.0f);
    for (int i = lane; i < 2 * AHALF; i += 32)
        myA[i] = ((i % ASTR) == 52) ? h1v : h0v;
    if (lane < 16)
        myA[lane * ASTR + 51] = __float2half_rn(x[(size_t)(rowbase + lane) * TSEQ]);
    float xnext = (lane < 16) ? x[(size_t)(rowbase + lane) * TSEQ + 1] : 0.0f;

    __syncthreads();                                // weights visible; ONLY CTA barrier

    const float bo = bout[0];
    float woj[13];
#pragma unroll
    for (int p = 0; p < 13; p++) {
        int j = 4 * p + tig;
        woj[p] = (j < 51) ? Wout[j] : 0.0f;
    }
    float creg[13][2];
#pragma unroll
    for (int p = 0; p < 13; p++) { creg[p][0] = 0.0f; creg[p][1] = 0.0f; }

    // ldmatrix per-lane byte offset within an A buffer
    const int lm = lane >> 3;
    const uint32_t aOff = (uint32_t)((((lm & 1) * 8 + (lane & 7)) * ASTR +
                                      (lm >> 1) * 8) * 2);
    uint32_t awAddr[2];
    awAddr[0] = (uint32_t)__cvta_generic_to_shared(myA);
    awAddr[1] = awAddr[0] + AHALF * 2;

    const uint4* W1 = Wsm;            // layer-1 base
    const uint4* W2 = Wsm + 2048;     // layer-2 base

// L2 p-body: racc accumulation with OLD creg (c is not updated)
#define PBODY_L2(p)                                                           \
    {                                                                         \
        float eA0 = 0.f, eA1 = 0.f, eA2 = 0.f, eA3 = 0.f;                     \
        float eB0 = 0.f, eB1 = 0.f, eB2 = 0.f, eB3 = 0.f;                     \
        MMA_PAIR(W2 + (p) * 128, eA0, eA1, eA2, eA3, eB0, eB1, eB2, eB3);     \
        float i2, f2, z2, o2;                                                 \
        site_act(eA0, eA1, eB0, eB1, i2, f2, z2, o2);                         \
        float c2 = fmaf(f2, creg[p][0], i2 * z2);                             \
        racc0 += o2 * tanh_ap(c2) * woj[p];                                   \
        site_act(eA2, eA3, eB2, eB3, i2, f2, z2, o2);                         \
        c2 = fmaf(f2, creg[p][1], i2 * z2);                                   \
        racc1 += o2 * tanh_ap(c2) * woj[p];                                   \
    }

// L1 p-body: creg update + h store into An
#define PBODY_L1(p, An)                                                       \
    {                                                                         \
        float dA0 = 0.f, dA1 = 0.f, dA2 = 0.f, dA3 = 0.f;                     \
        float dB0 = 0.f, dB1 = 0.f, dB2 = 0.f, dB3 = 0.f;                     \
        MMA_PAIR(W1 + (p) * 128, dA0, dA1, dA2, dA3, dB0, dB1, dB2, dB3);     \
        const int j = 4 * (p) + tig;                                          \
        float i1, f1, z1, o1;                                                 \
        site_act(dA0, dA1, dB0, dB1, i1, f1, z1, o1);                         \
        float c = fmaf(f1, creg[p][0], i1 * z1);                              \
        creg[p][0] = c;                                                       \
        if (j < 51) (An)[g * ASTR + j] = __float2half_rn(o1 * tanh_ap(c));    \
        site_act(dA2, dA3, dB2, dB3, i1, f1, z1, o1);                         \
        c = fmaf(f1, creg[p][1], i1 * z1);                                    \
        creg[p][1] = c;                                                       \
        if (j < 51) (An)[(g + 8) * ASTR + j] = __float2half_rn(o1 * tanh_ap(c)); \
    }

    // ================= main phase: k = 0..TSEQ-1, NO barriers ===============
    // iter k: A = [h(k-1), x(k), 1]. L2 -> out(k-1) (old creg); L1 -> h(k),
    // c(k). h(k) + x(k+1) staged into the other buffer; __syncwarp only.
#pragma unroll 1
    for (int k = 0; k < TSEQ; k++) {
        const uint32_t curA = awAddr[k & 1];
        __half* An = myA + ((k & 1) ^ 1) * AHALF;
        uint32_t a[4][4];
#pragma unroll
        for (int kt = 0; kt < 4; kt++)
            LDSM4(a[kt], curA + aOff + (uint32_t)(kt * 32));
        float racc0 = 0.f, racc1 = 0.f;
#pragma unroll
        for (int p = 0; p < 13; p++) {
            PBODY_L2(p)
            PBODY_L1(p, An)
        }
        if (lane < 16) {
            if (k + 1 < TSEQ)
                An[lane * ASTR + 51] = __float2half_rn(xnext);
            if (k + 2 < TSEQ)
                xnext = x[(size_t)(rowbase + lane) * TSEQ + (k + 2)];
        }
        __syncwarp();
        // emit out(k-1): reduce over the 4 tig lanes
        racc0 += __shfl_xor_sync(0xffffffffu, racc0, 1);
        racc0 += __shfl_xor_sync(0xffffffffu, racc0, 2);
        racc1 += __shfl_xor_sync(0xffffffffu, racc1, 1);
        racc1 += __shfl_xor_sync(0xffffffffu, racc1, 2);
        if (k >= 1 && tig == 0) {
            out[(size_t)(rowbase + g) * TTOT + (k - 1)]     = racc0 + bo;
            out[(size_t)(rowbase + g + 8) * TTOT + (k - 1)] = racc1 + bo;
        }
    }

    // ================= autoregressive tail (warp-local) =====================
#pragma unroll 1
    for (int t = TSEQ; t < TTOT; t++) {
        const uint32_t curA = awAddr[t & 1];
        __half* Ac = myA + (t & 1) * AHALF;
        __half* An = myA + ((t & 1) ^ 1) * AHALF;
        uint32_t a[4][4];
#pragma unroll
        for (int kt = 0; kt < 4; kt++)
            LDSM4(a[kt], curA + aOff + (uint32_t)(kt * 32));
        float racc0 = 0.f, racc1 = 0.f;
#pragma unroll
        for (int p = 0; p < 13; p++) {
            PBODY_L2(p)
        }
        racc0 += __shfl_xor_sync(0xffffffffu, racc0, 1);
        racc0 += __shfl_xor_sync(0xffffffffu, racc0, 2);
        racc1 += __shfl_xor_sync(0xffffffffu, racc1, 1);
        racc1 += __shfl_xor_sync(0xffffffffu, racc1, 2);
        if (tig == 0) {
            float o0 = racc0 + bo, o1 = racc1 + bo;
            out[(size_t)(rowbase + g) * TTOT + (t - 1)]     = o0;
            out[(size_t)(rowbase + g + 8) * TTOT + (t - 1)] = o1;
            Ac[g * ASTR + 51]       = __float2half_rn(o0);   // feedback -> x slot
            Ac[(g + 8) * ASTR + 51] = __float2half_rn(o1);
        }
        __syncwarp();
        // reload kt=3 fragment (contains the x slot) with the fed-back value
        LDSM1(a[3], curA + aOff + (uint32_t)(3 * 32));
#pragma unroll
        for (int p = 0; p < 13; p++) {
            PBODY_L1(p, An)
        }
        __syncwarp();
    }

    // ================= final emit: out(TTOT-1) ==============================
    {
        const uint32_t curA = awAddr[TTOT & 1];
        uint32_t a[4][4];
#pragma unroll
        for (int kt = 0; kt < 4; kt++)
            LDSM4(a[kt], curA + aOff + (uint32_t)(kt * 32));
        float racc0 = 0.f, racc1 = 0.f;
#pragma unroll
        for (int p = 0; p < 13; p++) {
            PBODY_L2(p)
        }
        racc0 += __shfl_xor_sync(0xffffffffu, racc0, 1);
        racc0 += __shfl_xor_sync(0xffffffffu, racc0, 2);
        racc1 += __shfl_xor_sync(0xffffffffu, racc1, 1);
        racc1 += __shfl_xor_sync(0xffffffffu, racc1, 2);
        if (tig == 0) {
            out[(size_t)(rowbase + g) * TTOT + (TTOT - 1)]     = racc0 + bo;
            out[(size_t)(rowbase + g + 8) * TTOT + (TTOT - 1)] = racc1 + bo;
        }
    }
}

// ---------------------------------------------------------------------------
extern "C" void kernel_launch(void* const* d_in, const int* in_sizes, int n_in,
                              void* d_out, int out_size) {
    const float* x    = (const float*)d_in[0];
    const float* Wih1 = (const float*)d_in[1];
    const float* Whh1 = (const float*)d_in[2];
    const float* bih1 = (const float*)d_in[3];
    const float* bhh1 = (const float*)d_in[4];
    const float* Wih2 = (const float*)d_in[5];
    const float* Whh2 = (const float*)d_in[6];
    const float* bih2 = (const float*)d_in[7];
    const float* bhh2 = (const float*)d_in[8];
    const float* Wout = (const float*)d_in[9];
    const float* bouT = (const float*)d_in[10];
    float* out = (float*)d_out;

    const int smem = 65536 + 4 * 2 * AHALF * 2;     // 83968 B
    cudaFuncSetAttribute(lstm_main, cudaFuncAttributeMaxDynamicSharedMemorySize, smem);

    prep_weights<<<64, 256>>>(Wih1, Whh1, bih1, bhh1, Wih2, Whh2, bih2, bhh2);
    lstm_main<<<NCTA, TPB, smem>>>(x, Wout, bouT, out);
}